// round 16
// baseline (speedup 1.0000x reference)
#include <cuda_runtime.h>

// Problem constants (fixed shapes)
#define DD    2048       // hidden dim
#define NTOK  16384      // B*T
#define NE    18         // 16 expert rows + 2 group rows
#define TE    9          // experts per half-warp
#define TT    4          // tokens per warp
#define THRV  0.15f
#define ROWU  512        // ulonglong2 (16B units) per W/x row
#define CU    16         // ulonglong2 per chunk per row (64 floats)
#define NCH   32         // chunks over D
#define RING  4          // cp.async W ring depth
#define TOKB  16         // tokens per block (4 warps x 4 tokens)

// Global scratch (no cudaMalloc). Zeroed at load; last block resets after use.
__device__ int g_counts[16];
__device__ unsigned int g_done;

__device__ __forceinline__ unsigned long long ffma2u(
    unsigned long long a, unsigned long long b, unsigned long long c) {
    unsigned long long d;
    asm("fma.rn.f32x2 %0, %1, %2, %3;" : "=l"(d) : "l"(a), "l"(b), "l"(c));
    return d;
}

__device__ __forceinline__ float pairsum(unsigned long long v) {
    float2 f = *reinterpret_cast<float2*>(&v);
    return f.x + f.y;
}

__device__ __forceinline__ void cp16(void* s, const void* g) {
    unsigned sa = (unsigned)__cvta_generic_to_shared(s);
    asm volatile("cp.async.cg.shared.global [%0], [%1], 16;"
                 :: "r"(sa), "l"(g) : "memory");
}
#define CP_COMMIT()  asm volatile("cp.async.commit_group;" ::: "memory")
#define CP_WAIT(n)   asm volatile("cp.async.wait_group %0;" :: "n"(n) : "memory")

// 128 threads = 4 warps; warp = 2 halves of 16 lanes.
// Halves share the warp's 4 tokens and split experts (0-8 / 9-17).
// W staged via cp.async ring (shared); x streamed straight to registers.
__global__ void __launch_bounds__(128, 4) egr_router_kernel(
    const float* __restrict__ x,
    const float* __restrict__ We,    // [16, D]
    const float* __restrict__ Wg,    // [2, D]
    float* __restrict__ out)
{
    __shared__ ulonglong2 wsl[RING][NE][CU];    // 18432 B  W ring
    __shared__ float sc[TOKB][NE + 1];
    __shared__ int hist[16];
    __shared__ bool isLast;

    const int tid  = threadIdx.x;
    if (tid < 16) hist[tid] = 0;

    const int warp  = tid >> 5;
    const int lane  = tid & 31;
    const int h     = lane >> 4;         // half: 0/1 -> expert split
    const int r     = lane & 15;         // 16B-unit within chunk
    const int ebase = h * TE;
    const int tw    = warp * TT;         // local token base

    const ulonglong2* Xu  = reinterpret_cast<const ulonglong2*>(x)
                            + ((size_t)blockIdx.x * TOKB + tw) * ROWU;
    const ulonglong2* Weu = reinterpret_cast<const ulonglong2*>(We);
    const ulonglong2* Wgu = reinterpret_cast<const ulonglong2*>(Wg);

    // ---- async stage of W chunk c into ring slot c&3 (288 x 16B) ----
    auto stage = [&](int c) {
        const int s = c & (RING - 1);
        #pragma unroll
        for (int k = 0; k < 3; k++) {
            const int idx = tid + (k << 7);
            if (idx < NE * CU) {
                const int row = idx >> 4, u = idx & 15;
                const ulonglong2* src = (row < 16)
                    ? (Weu + (size_t)row * ROWU)
                    : (Wgu + (size_t)(row - 16) * ROWU);
                cp16(&wsl[s][row][u], src + c * CU + u);
            }
        }
        CP_COMMIT();
    };

    unsigned long long acc[TE][TT];
    #pragma unroll
    for (int i = 0; i < TE; i++)
        #pragma unroll
        for (int t = 0; t < TT; t++) acc[i][t] = 0ull;

    stage(0); stage(1); stage(2);        // 3 W groups in flight

    // x register ring, depth 2 chunks (halves read same addr -> coalescer dedup)
    ulonglong2 xr[TT], xn[TT];
    #pragma unroll
    for (int t = 0; t < TT; t++) xr[t] = __ldcs(Xu + (size_t)t * ROWU + r);
    #pragma unroll
    for (int t = 0; t < TT; t++) xn[t] = __ldcs(Xu + (size_t)t * ROWU + CU + r);

    #pragma unroll 1
    for (int c = 0; c < NCH; c++) {
        CP_WAIT(2);                      // W chunk c complete (this thread)
        __syncthreads();                 // ...and visible block-wide

        if (c + 3 < NCH) stage(c + 3);   // refill slot consumed at iter c-1
        else CP_COMMIT();                // keep group count uniform

        const int s = c & (RING - 1);
        #pragma unroll
        for (int i = 0; i < TE; i++) {
            ulonglong2 w = wsl[s][ebase + i][r];    // LDS.128, conflict-free
            #pragma unroll
            for (int t = 0; t < TT; t++) {
                acc[i][t] = ffma2u(xr[t].x, w.x, acc[i][t]);
                acc[i][t] = ffma2u(xr[t].y, w.y, acc[i][t]);
            }
        }

        // rotate x ring; issue chunk c+2 loads (cover ~1 full chunk of compute)
        #pragma unroll
        for (int t = 0; t < TT; t++) xr[t] = xn[t];
        if (c + 2 < NCH) {
            #pragma unroll
            for (int t = 0; t < TT; t++)
                xn[t] = __ldcs(Xu + (size_t)t * ROWU + (c + 2) * CU + r);
        }
    }
    CP_WAIT(0);                          // drain before exit path

    // Reduce each partial over the 16 lanes of the half (stays within half)
    #pragma unroll
    for (int i = 0; i < TE; i++)
        #pragma unroll
        for (int t = 0; t < TT; t++) {
            float v = pairsum(acc[i][t]);
            v += __shfl_xor_sync(0xffffffffu, v, 8);
            v += __shfl_xor_sync(0xffffffffu, v, 4);
            v += __shfl_xor_sync(0xffffffffu, v, 2);
            v += __shfl_xor_sync(0xffffffffu, v, 1);
            if (r == 0) sc[tw + t][ebase + i] = v;
        }
    __syncthreads();

    // 16 router threads: one token each
    if (tid < 16) {
        float s[NE];
        #pragma unroll
        for (int e = 0; e < NE; e++) s[e] = sc[tid][e];
        const int tok = blockIdx.x * TOKB + tid;

        const float g0 = 1.f / (1.f + expf(-s[16]));
        const float g1 = 1.f / (1.f + expf(-s[17]));

        // Group A: experts 0..7, top-1 softmax prob
        float ma = s[0]; int ai = 0;
        #pragma unroll
        for (int j = 1; j < 8; j++) if (s[j] > ma) { ma = s[j]; ai = j; }
        float dena = 0.f;
        #pragma unroll
        for (int j = 0; j < 8; j++) dena += expf(s[j] - ma);
        const float aw = 1.f / dena;

        // Group B: experts 8..11
        float mb = s[8]; int bi = 0;
        #pragma unroll
        for (int j = 1; j < 4; j++) if (s[8 + j] > mb) { mb = s[8 + j]; bi = j; }
        float denb = 0.f;
        #pragma unroll
        for (int j = 0; j < 4; j++) denb += expf(s[8 + j] - mb);
        const float bact = (g0 > THRV) ? 1.f : 0.f;
        const float bw = (1.f / denb) * g0 * bact;

        // Group C: experts 12..15, top-2 (first-occurrence tie-break)
        float b1 = s[12]; int i1 = 0;
        float b2 = -3.402823466e+38f; int i2 = 0;
        #pragma unroll
        for (int j = 1; j < 4; j++) {
            float v = s[12 + j];
            if (v > b1)      { b2 = b1; i2 = i1; b1 = v; i1 = j; }
            else if (v > b2) { b2 = v;  i2 = j; }
        }
        float denc = 0.f;
        #pragma unroll
        for (int j = 0; j < 4; j++) denc += expf(s[12 + j] - b1);
        const float cact = (g1 > THRV) ? 1.f : 0.f;
        const float cg   = g1 * cact;
        const float cw0  = (1.f / denc) * cg;
        const float cw1  = (expf(b2 - b1) / denc) * cg;

        // Normalize & write
        const float inv = 1.f / (aw + bw + cw0 + cw1 + 1e-8f);
        float* ow = out + (size_t)tok * 6;
        ow[0] = aw  * inv;
        ow[1] = bw  * inv;
        ow[2] = cw0 * inv;
        ow[3] = cw1 * inv;
        ow[4] = 0.f;
        ow[5] = 0.f;

        float* oi = out + (size_t)NTOK * 6 + (size_t)tok * 6;
        oi[0] = (float)ai;
        oi[1] = (float)(8 + bi);
        oi[2] = (float)(12 + i1);
        oi[3] = (float)(12 + i2);
        oi[4] = 0.f;
        oi[5] = 0.f;

        atomicAdd(&hist[ai],      1);
        atomicAdd(&hist[8 + bi],  1);
        atomicAdd(&hist[12 + i1], 1);
        atomicAdd(&hist[12 + i2], 1);
    }

    __syncthreads();
    if (tid < 16) {
        atomicAdd(&g_counts[tid], hist[tid]);
        __threadfence();                 // publish before the done-ticket
    }
    __syncthreads();
    if (tid == 0) {
        unsigned v = atomicAdd(&g_done, 1u);
        isLast = (v == gridDim.x - 1);
    }
    __syncthreads();

    // Last block computes the aux loss and resets global scratch
    if (isLast && tid == 0) {
        __threadfence();
        const float total = 6.0f * (float)NTOK;
        const float u  = 1.0f / 16.0f;
        const float lu = logf(u);
        float aux = 0.f;
        #pragma unroll
        for (int e = 0; e < 16; e++) {
            float c = (float)g_counts[e] + (e == 0 ? 2.0f * (float)NTOK : 0.0f);
            aux += u * (lu - logf(c / total));
            g_counts[e] = 0;            // reset for next replay
        }
        out[(size_t)2 * NTOK * 6] = aux * 0.01f;
        g_done = 0;
    }
}

extern "C" void kernel_launch(void* const* d_in, const int* in_sizes, int n_in,
                              void* d_out, int out_size) {
    const float* x  = (const float*)d_in[0];   // (4,4096,2048) f32
    const float* We = (const float*)d_in[1];   // (16,2048) f32
    const float* Wg = (const float*)d_in[2];   // (2,2048) f32
    float* out = (float*)d_out;                // weights | indices | aux

    egr_router_kernel<<<NTOK / TOKB, 128>>>(x, We, Wg, out);
}

// round 17
// speedup vs baseline: 2.5274x; 2.5274x over previous
#include <cuda_runtime.h>

// Problem constants (fixed shapes)
#define DD    2048       // hidden dim
#define NTOK  16384      // B*T
#define NE    18         // 16 expert rows + 2 group rows
#define TE    9          // experts per half-warp
#define TT    4          // tokens per warp
#define THRV  0.15f
#define ROWU  512        // ulonglong2 (16B units) per W/x row
#define CU    32         // ulonglong2 per chunk per row (128 floats)
#define NCH   16         // chunks over D
#define RING  3          // cp.async ring depth (min for 1-barrier pattern)
#define TOKB  16         // tokens per block (4 warps x 4 tokens)

// dynamic smem byte offsets
#define OFF_W   0
#define W_BYTES (RING * NE * CU * 16)            // 27648
#define OFF_X   (OFF_W + W_BYTES)
#define X_BYTES (RING * TOKB * CU * 16)          // 24576
#define OFF_SC  (OFF_X + X_BYTES)                // float[16][19]
#define OFF_HIST (OFF_SC + TOKB * 19 * 4)
#define OFF_FLAG (OFF_HIST + 64)
#define SM_TOTAL (OFF_FLAG + 16)

// Global scratch (no cudaMalloc). Zeroed at load; last block resets after use.
__device__ int g_counts[16];
__device__ unsigned int g_done;

__device__ __forceinline__ unsigned long long ffma2u(
    unsigned long long a, unsigned long long b, unsigned long long c) {
    unsigned long long d;
    asm("fma.rn.f32x2 %0, %1, %2, %3;" : "=l"(d) : "l"(a), "l"(b), "l"(c));
    return d;
}

__device__ __forceinline__ float pairsum(unsigned long long v) {
    float2 f = *reinterpret_cast<float2*>(&v);
    return f.x + f.y;
}

__device__ __forceinline__ void cp16(void* s, const void* g) {
    unsigned sa = (unsigned)__cvta_generic_to_shared(s);
    asm volatile("cp.async.cg.shared.global [%0], [%1], 16;"
                 :: "r"(sa), "l"(g) : "memory");
}
#define CP_COMMIT()  asm volatile("cp.async.commit_group;" ::: "memory")
#define CP_WAIT(n)   asm volatile("cp.async.wait_group %0;" :: "n"(n) : "memory")

// 128 threads = 4 warps; warp = 2 halves of 16 lanes.
// Halves share the warp's 4 tokens and split experts (0-8 / 9-17).
__global__ void __launch_bounds__(128, 4) egr_router_kernel(
    const float* __restrict__ x,
    const float* __restrict__ We,    // [16, D]
    const float* __restrict__ Wg,    // [2, D]
    float* __restrict__ out)
{
    extern __shared__ char smem[];
    ulonglong2* wsl = (ulonglong2*)(smem + OFF_W);   // [RING][NE][CU]
    ulonglong2* xsl = (ulonglong2*)(smem + OFF_X);   // [RING][TOKB][CU]
    float (*sc)[19] = (float (*)[19])(smem + OFF_SC);
    int* hist       = (int*)(smem + OFF_HIST);
    int* flag       = (int*)(smem + OFF_FLAG);

    const int tid  = threadIdx.x;
    if (tid < 16) hist[tid] = 0;

    const int warp  = tid >> 5;
    const int lane  = tid & 31;
    const int h     = lane >> 4;         // half: 0/1 -> expert split
    const int r     = lane & 15;         // 16B-unit within sub-step
    const int ebase = h * TE;
    const int tw    = warp * TT;         // local token base

    const ulonglong2* Xu  = reinterpret_cast<const ulonglong2*>(x)
                            + (size_t)blockIdx.x * TOKB * ROWU;
    const ulonglong2* Weu = reinterpret_cast<const ulonglong2*>(We);
    const ulonglong2* Wgu = reinterpret_cast<const ulonglong2*>(Wg);

    // ---- async stage of chunk c into ring slot c%3 ----
    auto stage = [&](int c) {
        const int s = c % RING;
        // W: 18 rows x 32 units = 576
        #pragma unroll
        for (int k = 0; k < 5; k++) {
            const int idx = tid + (k << 7);
            if (idx < NE * CU) {
                const int row = idx >> 5, u = idx & 31;
                const ulonglong2* src = (row < 16)
                    ? (Weu + (size_t)row * ROWU)
                    : (Wgu + (size_t)(row - 16) * ROWU);
                cp16(&wsl[(s * NE + row) * CU + u], src + c * CU + u);
            }
        }
        // x: 16 tokens x 32 units = 512
        #pragma unroll
        for (int k = 0; k < 4; k++) {
            const int idx = tid + (k << 7);
            const int tok = idx >> 5, u = idx & 31;
            cp16(&xsl[(s * TOKB + tok) * CU + u], Xu + (size_t)tok * ROWU + c * CU + u);
        }
        CP_COMMIT();
    };

    unsigned long long acc[TE][TT];
    #pragma unroll
    for (int i = 0; i < TE; i++)
        #pragma unroll
        for (int t = 0; t < TT; t++) acc[i][t] = 0ull;

    stage(0); stage(1);                  // 2 groups in flight

    #pragma unroll 1
    for (int c = 0; c < NCH; c++) {
        CP_WAIT(1);                      // chunk c complete (this thread)
        __syncthreads();                 // ...and visible block-wide

        if (c + 2 < NCH) stage(c + 2);   // slot (c+2)%3 consumed at iter c-1
        else CP_COMMIT();                // keep group accounting uniform

        const int s = c % RING;
        // 2 sub-steps of 16 units each; per sub-step 9 W-LDS + 72 FFMA2/warp
        #pragma unroll
        for (int j = 0; j < 2; j++) {
            const int u = (j << 4) + r;
            ulonglong2 xa[TT];
            #pragma unroll
            for (int t = 0; t < TT; t++)
                xa[t] = xsl[(s * TOKB + tw + t) * CU + u];   // broadcast across halves

            #pragma unroll
            for (int i = 0; i < TE; i++) {
                ulonglong2 w = wsl[(s * NE + ebase + i) * CU + u];  // LDS.128
                #pragma unroll
                for (int t = 0; t < TT; t++) {
                    acc[i][t] = ffma2u(xa[t].x, w.x, acc[i][t]);
                    acc[i][t] = ffma2u(xa[t].y, w.y, acc[i][t]);
                }
            }
        }
    }
    CP_WAIT(0);                          // drain before exit path

    // Reduce each partial over the 16 lanes of the half (stays within half)
    #pragma unroll
    for (int i = 0; i < TE; i++)
        #pragma unroll
        for (int t = 0; t < TT; t++) {
            float v = pairsum(acc[i][t]);
            v += __shfl_xor_sync(0xffffffffu, v, 8);
            v += __shfl_xor_sync(0xffffffffu, v, 4);
            v += __shfl_xor_sync(0xffffffffu, v, 2);
            v += __shfl_xor_sync(0xffffffffu, v, 1);
            if (r == 0) sc[tw + t][ebase + i] = v;
        }
    __syncthreads();

    // 16 router threads: one token each
    if (tid < 16) {
        float s[NE];
        #pragma unroll
        for (int e = 0; e < NE; e++) s[e] = sc[tid][e];
        const int tok = blockIdx.x * TOKB + tid;

        const float g0 = 1.f / (1.f + expf(-s[16]));
        const float g1 = 1.f / (1.f + expf(-s[17]));

        // Group A: experts 0..7, top-1 softmax prob
        float ma = s[0]; int ai = 0;
        #pragma unroll
        for (int j = 1; j < 8; j++) if (s[j] > ma) { ma = s[j]; ai = j; }
        float dena = 0.f;
        #pragma unroll
        for (int j = 0; j < 8; j++) dena += expf(s[j] - ma);
        const float aw = 1.f / dena;

        // Group B: experts 8..11
        float mb = s[8]; int bi = 0;
        #pragma unroll
        for (int j = 1; j < 4; j++) if (s[8 + j] > mb) { mb = s[8 + j]; bi = j; }
        float denb = 0.f;
        #pragma unroll
        for (int j = 0; j < 4; j++) denb += expf(s[8 + j] - mb);
        const float bact = (g0 > THRV) ? 1.f : 0.f;
        const float bw = (1.f / denb) * g0 * bact;

        // Group C: experts 12..15, top-2 (first-occurrence tie-break)
        float b1 = s[12]; int i1 = 0;
        float b2 = -3.402823466e+38f; int i2 = 0;
        #pragma unroll
        for (int j = 1; j < 4; j++) {
            float v = s[12 + j];
            if (v > b1)      { b2 = b1; i2 = i1; b1 = v; i1 = j; }
            else if (v > b2) { b2 = v;  i2 = j; }
        }
        float denc = 0.f;
        #pragma unroll
        for (int j = 0; j < 4; j++) denc += expf(s[12 + j] - b1);
        const float cact = (g1 > THRV) ? 1.f : 0.f;
        const float cg   = g1 * cact;
        const float cw0  = (1.f / denc) * cg;
        const float cw1  = (expf(b2 - b1) / denc) * cg;

        // Normalize & write
        const float inv = 1.f / (aw + bw + cw0 + cw1 + 1e-8f);
        float* ow = out + (size_t)tok * 6;
        ow[0] = aw  * inv;
        ow[1] = bw  * inv;
        ow[2] = cw0 * inv;
        ow[3] = cw1 * inv;
        ow[4] = 0.f;
        ow[5] = 0.f;

        float* oi = out + (size_t)NTOK * 6 + (size_t)tok * 6;
        oi[0] = (float)ai;
        oi[1] = (float)(8 + bi);
        oi[2] = (float)(12 + i1);
        oi[3] = (float)(12 + i2);
        oi[4] = 0.f;
        oi[5] = 0.f;

        atomicAdd(&hist[ai],      1);
        atomicAdd(&hist[8 + bi],  1);
        atomicAdd(&hist[12 + i1], 1);
        atomicAdd(&hist[12 + i2], 1);
    }

    __syncthreads();
    if (tid < 16) {
        atomicAdd(&g_counts[tid], hist[tid]);
        __threadfence();                 // publish before the done-ticket
    }
    __syncthreads();
    if (tid == 0) {
        unsigned v = atomicAdd(&g_done, 1u);
        *flag = (v == gridDim.x - 1) ? 1 : 0;
    }
    __syncthreads();

    // Last block computes the aux loss and resets global scratch
    if (*flag && tid == 0) {
        __threadfence();
        const float total = 6.0f * (float)NTOK;
        const float u  = 1.0f / 16.0f;
        const float lu = logf(u);
        float aux = 0.f;
        #pragma unroll
        for (int e = 0; e < 16; e++) {
            float c = (float)g_counts[e] + (e == 0 ? 2.0f * (float)NTOK : 0.0f);
            aux += u * (lu - logf(c / total));
            g_counts[e] = 0;            // reset for next replay
        }
        out[(size_t)2 * NTOK * 6] = aux * 0.01f;
        g_done = 0;
    }
}

extern "C" void kernel_launch(void* const* d_in, const int* in_sizes, int n_in,
                              void* d_out, int out_size) {
    const float* x  = (const float*)d_in[0];   // (4,4096,2048) f32
    const float* We = (const float*)d_in[1];   // (16,2048) f32
    const float* Wg = (const float*)d_in[2];   // (2,2048) f32
    float* out = (float*)d_out;                // weights | indices | aux

    cudaFuncSetAttribute(egr_router_kernel,
                         cudaFuncAttributeMaxDynamicSharedMemorySize, SM_TOTAL);
    egr_router_kernel<<<NTOK / TOKB, 128, SM_TOTAL>>>(x, We, Wg, out);
}